// round 15
// baseline (speedup 1.0000x reference)
#include <cuda_runtime.h>
#include <cstdint>

#define BB 32
#define TT 4096
#define HH 256
#define STRIP_ROWS 16
#define STRIPS (BB * TT / STRIP_ROWS)       // 8192 strips of 16 KB
#define STRIPS_PER_BATCH (TT / STRIP_ROWS)  // 256
#define NTHREADS 256
#define NWARPS 8
#define OCC 3
#define GRID (148 * OCC)                    // 444: one wave at occ=3
#define PF 4                                // rows in flight per warp

#define ALPHA 0.1f
#define LOG2_09 (-0.15200309344504997f)
#define MASK_PENALTY 1000000.0f

__device__ float g_partial[STRIPS];
__device__ unsigned int g_work = 0;
__device__ unsigned int g_done = 0;

__global__ __launch_bounds__(NTHREADS, OCC)
void pool_warp(const float* __restrict__ x,
               const int*   __restrict__ mask,
               const float* __restrict__ weight_ema,
               const float* __restrict__ weight_mean,
               const float* __restrict__ W,
               const float* __restrict__ bias,
               float*       __restrict__ out)
{
    const int tid  = threadIdx.x;
    const int wid  = tid >> 5;
    const int lane = tid & 31;

    __shared__ bool s_is_last;

    // Per-lane W slices (each lane owns 8 of the 256 W values, split halves)
    const float4* W4 = reinterpret_cast<const float4*>(W);
    const float4 wa = __ldg(W4 + lane);        // W[lane*4 .. +3]
    const float4 wb = __ldg(W4 + 32 + lane);   // W[128 + lane*4 .. +3]

    float wsum = wa.x + wa.y + wa.z + wa.w + wb.x + wb.y + wb.z + wb.w;
    #pragma unroll
    for (int off = 16; off > 0; off >>= 1)
        wsum += __shfl_xor_sync(0xffffffffu, wsum, off);

    const float we        = __ldg(weight_ema);
    const float wm_over_T = __ldg(weight_mean) * (1.0f / (float)TT);
    const float cs        = we * ALPHA;
    const float penw      = MASK_PENALTY * wsum;

    const float4* x4 = reinterpret_cast<const float4*>(x);

    // ---- warp-autonomous work loop: one 16-row strip per ticket, no CTA syncs ----
    while (true) {
        int strip;
        if (lane == 0) strip = (int)atomicAdd(&g_work, 1u);
        strip = __shfl_sync(0xffffffffu, strip, 0);
        if (strip >= STRIPS) break;

        // strips are contiguous in the flattened (b,t) space
        const float4* base = x4 + (size_t)strip * STRIP_ROWS * (HH / 4);
        const int     f0   = strip * STRIP_ROWS;       // flattened b*TT + t
        const int     t0   = f0 & (TT - 1);            // t of first row

        // mask bits for the 16 rows (one load + ballot)
        int mv = (lane < STRIP_ROWS) ? __ldg(mask + f0 + lane) : 1;
        const unsigned penbits =
            __ballot_sync(0xffffffffu, (lane < STRIP_ROWS) && (mv == 0));

        float acc = 0.0f, pen_sum = 0.0f;

        // rotating 4-deep prefetch (8 LDG.128 in flight)
        float4 Abuf[PF], Cbuf[PF];
        #pragma unroll
        for (int k = 0; k < PF; k++) {
            const float4* p = base + (size_t)k * (HH / 4);
            Abuf[k] = __ldg(p + lane);
            Cbuf[k] = __ldg(p + 32 + lane);
        }

        #pragma unroll
        for (int i = 0; i < STRIP_ROWS; i++) {
            const int s = i & (PF - 1);
            float4 a  = Abuf[s];
            float4 c2 = Cbuf[s];
            if (i + PF < STRIP_ROWS) {
                const float4* p = base + (size_t)(i + PF) * (HH / 4);
                Abuf[s] = __ldg(p + lane);
                Cbuf[s] = __ldg(p + 32 + lane);
            }

            const int t = t0 + i;
            float wt = exp2f((float)(TT - 1 - t) * LOG2_09);
            float c  = (t == 0) ? fmaf(we, wt, wm_over_T)
                                : fmaf(cs, wt, wm_over_T);

            float p0 = a.x * wa.x;
            float p1 = a.y * wa.y;
            p0 = fmaf(a.z,  wa.z, p0);
            p1 = fmaf(a.w,  wa.w, p1);
            p0 = fmaf(c2.x, wb.x, p0);
            p1 = fmaf(c2.y, wb.y, p1);
            p0 = fmaf(c2.z, wb.z, p0);
            p1 = fmaf(c2.w, wb.w, p1);

            acc = fmaf(c, p0 + p1, acc);
            if ((penbits >> i) & 1u) pen_sum += c;
        }

        // one butterfly per strip (fixed order -> deterministic)
        #pragma unroll
        for (int off = 16; off > 0; off >>= 1)
            acc += __shfl_xor_sync(0xffffffffu, acc, off);

        if (lane == 0) g_partial[strip] = acc - pen_sum * penw;
    }

    // ---- completion: make this warp's stores visible, then CTA ticket ----
    __threadfence();
    __syncthreads();
    if (tid == 0) {
        unsigned ticket = atomicAdd(&g_done, 1u);
        s_is_last = (ticket == (unsigned)(GRID - 1));
    }
    __syncthreads();

    // ---- last CTA folds 8192 strip partials -> 32 outputs ----
    if (s_is_last) {
        const float bv = __ldg(bias);
        // 8 warps x 4 batches; each batch folds 256 strip partials.
        #pragma unroll
        for (int k = 0; k < BB / NWARPS; k++) {
            const int bb = wid * (BB / NWARPS) + k;
            float v = 0.0f;
            #pragma unroll
            for (int m = 0; m < STRIPS_PER_BATCH / 32; m++)
                v += __ldcg(&g_partial[bb * STRIPS_PER_BATCH + m * 32 + lane]);
            #pragma unroll
            for (int off = 16; off > 0; off >>= 1)
                v += __shfl_xor_sync(0xffffffffu, v, off);
            if (lane == 0) out[bb] = v + bv;
        }
        if (tid == 0) { g_work = 0; g_done = 0; }   // reset for next replay
    }
}

extern "C" void kernel_launch(void* const* d_in, const int* in_sizes, int n_in,
                              void* d_out, int out_size)
{
    const float* x    = (const float*)d_in[0];
    const int*   mask = (const int*)d_in[1];
    const float* we   = (const float*)d_in[2];
    const float* wm   = (const float*)d_in[3];
    const float* W    = (const float*)d_in[4];
    const float* bias = (const float*)d_in[5];
    float* out = (float*)d_out;

    pool_warp<<<GRID, NTHREADS>>>(x, mask, we, wm, W, bias, out);
}